// round 7
// baseline (speedup 1.0000x reference)
#include <cuda_runtime.h>
#include <cuda_fp16.h>
#include <math.h>
#include <stdint.h>

// ---------------------------------------------------------------------------
// Swin block: 2-term split-fp16 HMMA GEMMs, BN=128 tiles (halved A traffic),
// fp16 qkv buffer, cp.async pipelines, fused epilogues, vectorized attention.
// ---------------------------------------------------------------------------

#define BATCH   64
#define HH      56
#define WW_     56
#define CC      192
#define WS_     7
#define SS_     3
#define NH_     6
#define HD_     32
#define NTOK    49
#define NWIN    4096
#define MROWS   200704
#define HIDDEN  768
#define EPS_    1e-5f

// ------------------------------- scratch -----------------------------------
__device__ __half g_ln  [(size_t)MROWS * 384];    // LN out, [hi192|lo192]
__device__ __half g_attn[(size_t)MROWS * 384];    // attn out, [hi192|lo192]
__device__ __half g_hid [(size_t)MROWS * 1536];   // GELU out, [hi768|lo768]
__device__ __half g_qkv [(size_t)MROWS * 576];    // window-order fp16
__device__ float g_xnew[(size_t)MROWS * CC];      // natural fp32
__device__ int   g_rowmap[MROWS];
// weights fp16 [NP][K], zero-padded rows; padded biases
__device__ __half g_wqkv [640 * 192];
__device__ __half g_wproj[256 * 192];
__device__ __half g_wfc1 [768 * 192];
__device__ __half g_wfc2 [256 * 768];
__device__ float g_bqkv[640], g_bproj[256], g_bfc1[768], g_bfc2[256];

// ------------------------------ helpers -------------------------------------
__device__ __forceinline__ uint32_t smem_u32(const void* p) {
    uint32_t a;
    asm("{ .reg .u64 t; cvta.to.shared.u64 t, %1; cvt.u32.u64 %0, t; }"
        : "=r"(a) : "l"(p));
    return a;
}
#define SWZ(o) ((o) ^ (((o) >> 3) & 0x70))

__device__ __forceinline__ void cp16(uint32_t dst, const void* src) {
    asm volatile("cp.async.cg.shared.global [%0], [%1], 16;"
                 :: "r"(dst), "l"(src));
}
__device__ __forceinline__ void cp_commit() {
    asm volatile("cp.async.commit_group;" ::: "memory");
}
__device__ __forceinline__ void cp_wait0() {
    asm volatile("cp.async.wait_group 0;" ::: "memory");
}
__device__ __forceinline__ void ldm4(uint32_t* r, uint32_t addr) {
    asm volatile("ldmatrix.sync.aligned.m8n8.x4.shared.b16 {%0,%1,%2,%3}, [%4];"
                 : "=r"(r[0]), "=r"(r[1]), "=r"(r[2]), "=r"(r[3]) : "r"(addr));
}
__device__ __forceinline__ void mma16816(float* c, const uint32_t* a,
                                         uint32_t b0, uint32_t b1) {
    asm volatile(
        "mma.sync.aligned.m16n8k16.row.col.f32.f16.f16.f32 "
        "{%0,%1,%2,%3}, {%4,%5,%6,%7}, {%8,%9}, {%0,%1,%2,%3};"
        : "+f"(c[0]), "+f"(c[1]), "+f"(c[2]), "+f"(c[3])
        : "r"(a[0]), "r"(a[1]), "r"(a[2]), "r"(a[3]), "r"(b0), "r"(b1));
}
__device__ __forceinline__ uint32_t h2u(__half2 v) { return *(uint32_t*)&v; }

// -------------------------- small prep kernels ------------------------------
__global__ void rowmap_kernel() {
    int m = blockIdx.x * 256 + threadIdx.x;
    if (m >= MROWS) return;
    int bwin = m / NTOK, tok = m - bwin * NTOK;
    int b  = bwin >> 6, w = bwin & 63;
    int wh = w >> 3, ww = w & 7;
    int r = tok / WS_, c = tok - r * WS_;
    int gh = wh * WS_ + r, gw = ww * WS_ + c;
    int oh = gh + SS_; if (oh >= HH)  oh -= HH;
    int ow = gw + SS_; if (ow >= WW_) ow -= WW_;
    g_rowmap[m] = (b * (HH * WW_) + oh * WW_ + ow);
}

// fp32 [K,N] -> fp16 [NP,K], zero rows >= Nd
__global__ void whalf_kernel(const float* __restrict__ W,
                             __half* __restrict__ out, int Kd, int Nd, int NP) {
    int idx = blockIdx.x * 256 + threadIdx.x;
    if (idx >= NP * Kd) return;
    int n = idx / Kd, k = idx - n * Kd;
    out[idx] = (n < Nd) ? __float2half(W[(size_t)k * Nd + n]) : __half(0);
}

__global__ void biaspad_kernel(const float* __restrict__ src,
                               float* __restrict__ dst, int Nd, int NP) {
    int i = blockIdx.x * 256 + threadIdx.x;
    if (i < NP) dst[i] = (i < Nd) ? src[i] : 0.f;
}

// LN: fp32 in -> split fp16 out ([hi192 | lo192] rows)
__global__ void ln_kernel(const float* __restrict__ in,
                          const float* __restrict__ w,
                          const float* __restrict__ b,
                          __half* __restrict__ out) {
    int row  = blockIdx.x * 8 + (threadIdx.x >> 5);
    int lane = threadIdx.x & 31;
    const float* p = in + (size_t)row * CC;
    float v[6];
    float s = 0.f;
#pragma unroll
    for (int i = 0; i < 6; i++) { v[i] = p[lane + 32 * i]; s += v[i]; }
#pragma unroll
    for (int o = 16; o > 0; o >>= 1) s += __shfl_xor_sync(0xffffffffu, s, o);
    float mean = s * (1.f / CC);
    float q = 0.f;
#pragma unroll
    for (int i = 0; i < 6; i++) { float d = v[i] - mean; q += d * d; }
#pragma unroll
    for (int o = 16; o > 0; o >>= 1) q += __shfl_xor_sync(0xffffffffu, q, o);
    float inv = rsqrtf(q * (1.f / CC) + EPS_);
    __half* op = out + (size_t)row * 384;
#pragma unroll
    for (int i = 0; i < 6; i++) {
        int c = lane + 32 * i;
        float y = (v[i] - mean) * inv * w[c] + b[c];
        __half h = __float2half(y);
        op[c]       = h;
        op[192 + c] = __float2half(y - __half2float(h));
    }
}

// ----------------------------- mma GEMM --------------------------------------
// C[128,128] tile = Asp[128,2K] x Bhi[NP,K]^T, terms: hiA*hiB + loA*hiB.
// BK=64 fp32-k per chunk, cp.async double buffer.
// stage: A-hi 16K | A-lo 16K | B-hi 16K = 48KB; 2 stages = 96KB dyn smem.
#define STAGE_B 49152
template<int K, int MODE, int NREAL>
__global__ __launch_bounds__(256, 2)
void mma_gemm(const __half* __restrict__ A,
              const __half* __restrict__ Bhi,
              const float* __restrict__ bias,
              const float* __restrict__ aux,
              float* __restrict__ outp)
{
    extern __shared__ __align__(128) char dynsm[];
    constexpr int NCH = K / 64;
    constexpr int ARS = 2 * K;

    const int tid  = threadIdx.x;
    const int lane = tid & 31;
    const int warp = tid >> 5;
    const int wm = warp & 3;        // 32-row slice
    const int wn = warp >> 2;       // 64-col slice
    const int blockN = blockIdx.x * 128;
    const int blockM = blockIdx.y * 128;
    const uint32_t sb0 = smem_u32(dynsm);

    // A cp.async descriptors (4 hi + 4 lo per thread)
    const __half* aSrc[4];
    uint32_t aDst[4];
#pragma unroll
    for (int i = 0; i < 4; i++) {
        int idx = i * 256 + tid;
        int row = idx >> 3, u = idx & 7;
        int garow = (MODE == 0) ? g_rowmap[blockM + row] : (blockM + row);
        aSrc[i] = A + (size_t)garow * ARS + u * 8;
        aDst[i] = SWZ((uint32_t)(row * 128 + u * 16));
    }
    // B cp.async (4 per thread: 128 rows x 8 cp16)
    const __half* bSrc[4];
    uint32_t bDst[4];
#pragma unroll
    for (int i = 0; i < 4; i++) {
        int idx = i * 256 + tid;
        int n = idx >> 3, u = idx & 7;
        bSrc[i] = Bhi + (size_t)(blockN + n) * K + u * 8;
        bDst[i] = SWZ((uint32_t)(n * 128 + u * 16));
    }

    auto issue = [&](int c, int st) {
        const uint32_t sb = sb0 + st * STAGE_B;
#pragma unroll
        for (int i = 0; i < 4; i++) {
            cp16(sb + aDst[i],         aSrc[i] + c * 64);
            cp16(sb + 16384 + aDst[i], aSrc[i] + K + c * 64);
        }
#pragma unroll
        for (int i = 0; i < 4; i++)
            cp16(sb + 32768 + bDst[i], bSrc[i] + c * 64);
    };

    uint32_t oA[2], oB[4];
#pragma unroll
    for (int tm = 0; tm < 2; tm++)
        oA[tm] = (uint32_t)((wm * 32 + tm * 16 + (lane & 15)) * 128 + (lane >> 4) * 16);
#pragma unroll
    for (int g = 0; g < 4; g++)
        oB[g] = (uint32_t)((wn * 64 + g * 16 + (lane & 7) + ((lane >> 4) & 1) * 8) * 128
                           + ((lane >> 3) & 1) * 16);

    float Cr[2][8][4];
#pragma unroll
    for (int a = 0; a < 2; a++)
#pragma unroll
        for (int b = 0; b < 8; b++)
#pragma unroll
            for (int c = 0; c < 4; c++) Cr[a][b][c] = 0.f;

    issue(0, 0);
    cp_commit();

    for (int c = 0; c < NCH; c++) {
        const int st = c & 1;
        cp_wait0();
        __syncthreads();
        if (c + 1 < NCH) { issue(c + 1, st ^ 1); cp_commit(); }

        const uint32_t aH = sb0 + st * STAGE_B;
        const uint32_t aL = aH + 16384;
        const uint32_t bH = aH + 32768;
#pragma unroll
        for (int k16 = 0; k16 < 4; k16++) {
            const uint32_t ko = k16 * 32;
            uint32_t Ah[2][4], Al[2][4], Bh[4][4];
#pragma unroll
            for (int tm = 0; tm < 2; tm++) {
                ldm4(Ah[tm], aH + SWZ(oA[tm] + ko));
                ldm4(Al[tm], aL + SWZ(oA[tm] + ko));
            }
#pragma unroll
            for (int g = 0; g < 4; g++)
                ldm4(Bh[g], bH + SWZ(oB[g] + ko));
#pragma unroll
            for (int tm = 0; tm < 2; tm++)
#pragma unroll
                for (int tn = 0; tn < 8; tn++)
                    mma16816(Cr[tm][tn], Ah[tm],
                             Bh[tn >> 1][(tn & 1) * 2], Bh[tn >> 1][(tn & 1) * 2 + 1]);
#pragma unroll
            for (int tm = 0; tm < 2; tm++)
#pragma unroll
                for (int tn = 0; tn < 8; tn++)
                    mma16816(Cr[tm][tn], Al[tm],
                             Bh[tn >> 1][(tn & 1) * 2], Bh[tn >> 1][(tn & 1) * 2 + 1]);
        }
        __syncthreads();
    }

    // ------------------------------ epilogue --------------------------------
    const int r0 = blockM + wm * 32 + (lane >> 2);
    const int n0 = blockN + wn * 64 + 2 * (lane & 3);
#pragma unroll
    for (int tm = 0; tm < 2; tm++) {
#pragma unroll
        for (int tn = 0; tn < 8; tn++) {
            int n = n0 + tn * 8;
            if (n >= NREAL) continue;
            float bx = bias[n], by = bias[n + 1];
#pragma unroll
            for (int half_ = 0; half_ < 2; half_++) {
                int m = r0 + tm * 16 + half_ * 8;
                float vx = Cr[tm][tn][half_ * 2 + 0] + bx;
                float vy = Cr[tm][tn][half_ * 2 + 1] + by;
                if (MODE == 0) {
                    *(__half2*)(g_qkv + (size_t)m * 576 + n) = __floats2half2_rn(vx, vy);
                } else if (MODE == 1) {
                    size_t idx = (size_t)g_rowmap[m] * CC + n;
                    float2 a = *(const float2*)(aux + idx);
                    *(float2*)(g_xnew + idx) = make_float2(vx + a.x, vy + a.y);
                } else if (MODE == 2) {
                    vx = 0.5f * vx * (1.f + erff(vx * 0.70710678118654752f));
                    vy = 0.5f * vy * (1.f + erff(vy * 0.70710678118654752f));
                    __half2 h = __floats2half2_rn(vx, vy);
                    __half2 l = __floats2half2_rn(vx - __half2float(__low2half(h)),
                                                  vy - __half2float(__high2half(h)));
                    __half* row = g_hid + (size_t)m * 1536;
                    *(uint32_t*)(row + n)       = h2u(h);
                    *(uint32_t*)(row + 768 + n) = h2u(l);
                } else {
                    size_t idx = (size_t)m * CC + n;
                    float2 a = *(const float2*)(g_xnew + idx);
                    *(float2*)(outp + idx) = make_float2(vx + a.x, vy + a.y);
                }
            }
        }
    }
}

// ------------------------------ attention -----------------------------------
__global__ __launch_bounds__(256)
void attn_kernel(const float* __restrict__ rpb) {
    __shared__ __align__(16) float sq[52 * 36];
    __shared__ __align__(16) float sk[52 * 36];
    __shared__ __align__(16) float sv[52 * 36];
    __shared__ float sS[NTOK * 50];
    __shared__ float srpb[169];
    __shared__ int   slabel[NTOK];

    const int bwin = blockIdx.x;
    const int head = blockIdx.y;
    const int tid  = threadIdx.x;
    const float scale = 0.17677669529663687f;

    const size_t rbase = (size_t)(bwin * NTOK) * 576 + head * HD_;
    for (int idx = tid; idx < NTOK * 16; idx += 256) {
        int tok = idx >> 4, d2 = (idx & 15) * 2;
        const __half* r = g_qkv + rbase + (size_t)tok * 576 + d2;
        float2 qf = __half22float2(*(const __half2*)r);
        float2 kf = __half22float2(*(const __half2*)(r + 192));
        float2 vf = __half22float2(*(const __half2*)(r + 384));
        float* qq = &sq[tok * 36 + d2];
        float* kk = &sk[tok * 36 + d2];
        float* vv = &sv[tok * 36 + d2];
        qq[0] = qf.x * scale; qq[1] = qf.y * scale;
        kk[0] = kf.x;         kk[1] = kf.y;
        vv[0] = vf.x;         vv[1] = vf.y;
    }
    for (int t = tid; t < 169; t += 256) srpb[t] = rpb[t * NH_ + head];
    if (tid < NTOK) {
        int w = bwin & 63;
        int wh = w >> 3, ww = w & 7;
        int r = tid / WS_, c = tid - r * WS_;
        int gh = wh * WS_ + r, gw = ww * WS_ + c;
        int rr = (gh < HH - WS_) ? 0 : (gh < HH - SS_) ? 1 : 2;
        int cc = (gw < WW_ - WS_) ? 0 : (gw < WW_ - SS_) ? 1 : 2;
        slabel[tid] = rr * 3 + cc;
    }
    for (int t = tid; t < 3 * 36; t += 256) {
        sk[49 * 36 + t] = 0.f;
        sv[49 * 36 + t] = 0.f;
    }
    __syncthreads();

    // S = q k^T + bias + mask (4 j per thread, float4 over d)
    for (int e = tid; e < NTOK * 13; e += 256) {
        int i = e / 13, j0 = (e - i * 13) * 4;
        float4 s0 = make_float4(0, 0, 0, 0), s1 = s0, s2 = s0, s3 = s0;
        const float4* q4 = (const float4*)&sq[i * 36];
        const float* kb = &sk[j0 * 36];
#pragma unroll
        for (int d4 = 0; d4 < 8; d4++) {
            float4 q = q4[d4];
            float4 k0 = *(const float4*)(kb + d4 * 4);
            float4 k1 = *(const float4*)(kb + 36 + d4 * 4);
            float4 k2 = *(const float4*)(kb + 72 + d4 * 4);
            float4 k3 = *(const float4*)(kb + 108 + d4 * 4);
            s0.x += q.x * k0.x; s0.y += q.y * k0.y; s0.z += q.z * k0.z; s0.w += q.w * k0.w;
            s1.x += q.x * k1.x; s1.y += q.y * k1.y; s1.z += q.z * k1.z; s1.w += q.w * k1.w;
            s2.x += q.x * k2.x; s2.y += q.y * k2.y; s2.z += q.z * k2.z; s2.w += q.w * k2.w;
            s3.x += q.x * k3.x; s3.y += q.y * k3.y; s3.z += q.z * k3.z; s3.w += q.w * k3.w;
        }
        float acc[4] = { s0.x + s0.y + s0.z + s0.w, s1.x + s1.y + s1.z + s1.w,
                         s2.x + s2.y + s2.z + s2.w, s3.x + s3.y + s3.z + s3.w };
        int ri = i / WS_, ci = i - ri * WS_;
        int li = slabel[i];
#pragma unroll
        for (int t = 0; t < 4; t++) {
            int j = j0 + t;
            if (j < NTOK) {
                int rj = j / WS_, cj = j - rj * WS_;
                float a = acc[t] + srpb[(ri - rj + 6) * 13 + (ci - cj + 6)];
                if (li != slabel[j]) a -= 100.f;
                sS[i * 50 + j] = a;
            }
        }
    }
    __syncthreads();

    // softmax: warp per row
    {
        int warp = tid >> 5, lane = tid & 31;
        for (int i = warp; i < NTOK; i += 8) {
            float mx = -1e30f;
            for (int j = lane; j < NTOK; j += 32) mx = fmaxf(mx, sS[i * 50 + j]);
#pragma unroll
            for (int o = 16; o > 0; o >>= 1) mx = fmaxf(mx, __shfl_xor_sync(0xffffffffu, mx, o));
            float s = 0.f;
            for (int j = lane; j < NTOK; j += 32) {
                float e = __expf(sS[i * 50 + j] - mx);
                sS[i * 50 + j] = e;
                s += e;
            }
#pragma unroll
            for (int o = 16; o > 0; o >>= 1) s += __shfl_xor_sync(0xffffffffu, s, o);
            float inv = 1.f / s;
            for (int j = lane; j < NTOK; j += 32) sS[i * 50 + j] *= inv;
        }
    }
    __syncthreads();

    // O = P V (float4 over d), split-fp16 out
    for (int e = tid; e < NTOK * 8; e += 256) {
        int i = e >> 3, d0 = (e & 7) * 4;
        float4 acc = make_float4(0, 0, 0, 0);
        const float* Si = &sS[i * 50];
        const float* vb = &sv[d0];
#pragma unroll
        for (int j = 0; j < NTOK; j++) {
            float s_ = Si[j];
            float4 v = *(const float4*)(vb + j * 36);
            acc.x += s_ * v.x; acc.y += s_ * v.y;
            acc.z += s_ * v.z; acc.w += s_ * v.w;
        }
        __half2 h01 = __floats2half2_rn(acc.x, acc.y);
        __half2 h23 = __floats2half2_rn(acc.z, acc.w);
        __half2 l01 = __floats2half2_rn(acc.x - __half2float(__low2half(h01)),
                                        acc.y - __half2float(__high2half(h01)));
        __half2 l23 = __floats2half2_rn(acc.z - __half2float(__low2half(h23)),
                                        acc.w - __half2float(__high2half(h23)));
        __half* row = g_attn + (size_t)(bwin * NTOK + i) * 384 + head * HD_ + d0;
        *(uint2*)row         = make_uint2(h2u(h01), h2u(h23));
        *(uint2*)(row + 192) = make_uint2(h2u(l01), h2u(l23));
    }
}

// ------------------------------- launch -------------------------------------
extern "C" void kernel_launch(void* const* d_in, const int* in_sizes, int n_in,
                              void* d_out, int out_size) {
    const float* x       = (const float*)d_in[0];
    const float* norm1_w = (const float*)d_in[1];
    const float* norm1_b = (const float*)d_in[2];
    const float* qkv_w   = (const float*)d_in[3];
    const float* qkv_b   = (const float*)d_in[4];
    const float* rpb     = (const float*)d_in[5];
    const float* proj_w  = (const float*)d_in[6];
    const float* proj_b  = (const float*)d_in[7];
    const float* norm2_w = (const float*)d_in[8];
    const float* norm2_b = (const float*)d_in[9];
    const float* fc1_w   = (const float*)d_in[10];
    const float* fc1_b   = (const float*)d_in[11];
    const float* fc2_w   = (const float*)d_in[12];
    const float* fc2_b   = (const float*)d_in[13];
    float* out = (float*)d_out;

    __half *p_ln, *p_attn, *p_hid, *p_wqkv, *p_wproj, *p_wfc1, *p_wfc2;
    float *p_xnew, *p_bqkv, *p_bproj, *p_bfc1, *p_bfc2;
    cudaGetSymbolAddress((void**)&p_ln,    g_ln);
    cudaGetSymbolAddress((void**)&p_attn,  g_attn);
    cudaGetSymbolAddress((void**)&p_hid,   g_hid);
    cudaGetSymbolAddress((void**)&p_xnew,  g_xnew);
    cudaGetSymbolAddress((void**)&p_wqkv,  g_wqkv);
    cudaGetSymbolAddress((void**)&p_wproj, g_wproj);
    cudaGetSymbolAddress((void**)&p_wfc1,  g_wfc1);
    cudaGetSymbolAddress((void**)&p_wfc2,  g_wfc2);
    cudaGetSymbolAddress((void**)&p_bqkv,  g_bqkv);
    cudaGetSymbolAddress((void**)&p_bproj, g_bproj);
    cudaGetSymbolAddress((void**)&p_bfc1,  g_bfc1);
    cudaGetSymbolAddress((void**)&p_bfc2,  g_bfc2);

    const int SMEM = 2 * STAGE_B;
    cudaFuncSetAttribute(mma_gemm<192,0,576>, cudaFuncAttributeMaxDynamicSharedMemorySize, SMEM);
    cudaFuncSetAttribute(mma_gemm<192,1,192>, cudaFuncAttributeMaxDynamicSharedMemorySize, SMEM);
    cudaFuncSetAttribute(mma_gemm<192,2,768>, cudaFuncAttributeMaxDynamicSharedMemorySize, SMEM);
    cudaFuncSetAttribute(mma_gemm<768,3,192>, cudaFuncAttributeMaxDynamicSharedMemorySize, SMEM);

    // order chosen so the QKV GEMM is the 6th launch (ncu -s 5 -c 1)
    rowmap_kernel<<<(MROWS + 255) / 256, 256>>>();
    ln_kernel<<<MROWS / 8, 256>>>(x, norm1_w, norm1_b, p_ln);
    whalf_kernel<<<(640 * 192 + 255) / 256, 256>>>(qkv_w, p_wqkv, 192, 576, 640);
    biaspad_kernel<<<3, 256>>>(qkv_b, p_bqkv, 576, 640);
    whalf_kernel<<<(256 * 192 + 255) / 256, 256>>>(proj_w, p_wproj, 192, 192, 256);

    mma_gemm<192, 0, 576><<<dim3(5, 1568), 256, SMEM>>>(p_ln, p_wqkv, p_bqkv, nullptr, nullptr);

    attn_kernel<<<dim3(NWIN, NH_), 256>>>(rpb);

    biaspad_kernel<<<1, 256>>>(proj_b, p_bproj, 192, 256);
    mma_gemm<192, 1, 192><<<dim3(2, 1568), 256, SMEM>>>(p_attn, p_wproj, p_bproj, x, nullptr);

    ln_kernel<<<MROWS / 8, 256>>>(p_xnew, norm2_w, norm2_b, p_ln);

    whalf_kernel<<<(768 * 192 + 255) / 256, 256>>>(fc1_w, p_wfc1, 192, 768, 768);
    biaspad_kernel<<<3, 256>>>(fc1_b, p_bfc1, 768, 768);
    mma_gemm<192, 2, 768><<<dim3(6, 1568), 256, SMEM>>>(p_ln, p_wfc1, p_bfc1, nullptr, nullptr);

    whalf_kernel<<<(256 * 768 + 255) / 256, 256>>>(fc2_w, p_wfc2, 768, 192, 256);
    biaspad_kernel<<<1, 256>>>(fc2_b, p_bfc2, 192, 256);
    mma_gemm<768, 3, 192><<<dim3(2, 1568), 256, SMEM>>>(p_hid, p_wfc2, p_bfc2, nullptr, out);
}

// round 8
// speedup vs baseline: 2.0048x; 2.0048x over previous
#include <cuda_runtime.h>
#include <cuda_fp16.h>
#include <math.h>
#include <stdint.h>

// ---------------------------------------------------------------------------
// Swin block: single-term fp16 HMMA GEMMs (3-stage cp.async pipeline),
// fp16-smem attention, fused epilogues.
// ---------------------------------------------------------------------------

#define BATCH   64
#define HH      56
#define WW_     56
#define CC      192
#define WS_     7
#define SS_     3
#define NH_     6
#define HD_     32
#define NTOK    49
#define NWIN    4096
#define MROWS   200704
#define HIDDEN  768
#define EPS_    1e-5f

// ------------------------------- scratch -----------------------------------
__device__ __half g_ln  [(size_t)MROWS * 192];    // LN out fp16
__device__ __half g_attn[(size_t)MROWS * 192];    // attn out fp16 (window order)
__device__ __half g_hid [(size_t)MROWS * 768];    // GELU out fp16
__device__ __half g_qkv [(size_t)MROWS * 576];    // window-order fp16
__device__ float g_xnew[(size_t)MROWS * CC];      // natural fp32
__device__ int   g_rowmap[MROWS];
// weights fp16 [NP][K], zero-padded rows
__device__ __half g_wqkv [640 * 192];
__device__ __half g_wproj[256 * 192];
__device__ __half g_wfc1 [768 * 192];
__device__ __half g_wfc2 [256 * 768];

// ------------------------------ helpers -------------------------------------
__device__ __forceinline__ uint32_t smem_u32(const void* p) {
    uint32_t a;
    asm("{ .reg .u64 t; cvta.to.shared.u64 t, %1; cvt.u32.u64 %0, t; }"
        : "=r"(a) : "l"(p));
    return a;
}
#define SWZ(o) ((o) ^ (((o) >> 3) & 0x70))

__device__ __forceinline__ void cp16(uint32_t dst, const void* src) {
    asm volatile("cp.async.cg.shared.global [%0], [%1], 16;"
                 :: "r"(dst), "l"(src));
}
__device__ __forceinline__ void cp_commit() {
    asm volatile("cp.async.commit_group;" ::: "memory");
}
__device__ __forceinline__ void cp_wait1() {
    asm volatile("cp.async.wait_group 1;" ::: "memory");
}
__device__ __forceinline__ void ldm4(uint32_t* r, uint32_t addr) {
    asm volatile("ldmatrix.sync.aligned.m8n8.x4.shared.b16 {%0,%1,%2,%3}, [%4];"
                 : "=r"(r[0]), "=r"(r[1]), "=r"(r[2]), "=r"(r[3]) : "r"(addr));
}
__device__ __forceinline__ void mma16816(float* c, const uint32_t* a,
                                         uint32_t b0, uint32_t b1) {
    asm volatile(
        "mma.sync.aligned.m16n8k16.row.col.f32.f16.f16.f32 "
        "{%0,%1,%2,%3}, {%4,%5,%6,%7}, {%8,%9}, {%0,%1,%2,%3};"
        : "+f"(c[0]), "+f"(c[1]), "+f"(c[2]), "+f"(c[3])
        : "r"(a[0]), "r"(a[1]), "r"(a[2]), "r"(a[3]), "r"(b0), "r"(b1));
}
__device__ __forceinline__ uint32_t h2u(__half2 v) { return *(uint32_t*)&v; }

// -------------------------- small prep kernels ------------------------------
__global__ void rowmap_kernel() {
    int m = blockIdx.x * 256 + threadIdx.x;
    if (m >= MROWS) return;
    int bwin = m / NTOK, tok = m - bwin * NTOK;
    int b  = bwin >> 6, w = bwin & 63;
    int wh = w >> 3, ww = w & 7;
    int r = tok / WS_, c = tok - r * WS_;
    int gh = wh * WS_ + r, gw = ww * WS_ + c;
    int oh = gh + SS_; if (oh >= HH)  oh -= HH;
    int ow = gw + SS_; if (ow >= WW_) ow -= WW_;
    g_rowmap[m] = (b * (HH * WW_) + oh * WW_ + ow);
}

// fp32 [K,N] -> fp16 [NP,K], zero rows >= Nd
__global__ void whalf_kernel(const float* __restrict__ W,
                             __half* __restrict__ out, int Kd, int Nd, int NP) {
    int idx = blockIdx.x * 256 + threadIdx.x;
    if (idx >= NP * Kd) return;
    int n = idx / Kd, k = idx - n * Kd;
    out[idx] = (n < Nd) ? __float2half(W[(size_t)k * Nd + n]) : __half(0);
}

// LN: fp32 in -> fp16 out
__global__ void ln_kernel(const float* __restrict__ in,
                          const float* __restrict__ w,
                          const float* __restrict__ b,
                          __half* __restrict__ out) {
    int row  = blockIdx.x * 8 + (threadIdx.x >> 5);
    int lane = threadIdx.x & 31;
    const float* p = in + (size_t)row * CC;
    float v[6];
    float s = 0.f;
#pragma unroll
    for (int i = 0; i < 6; i++) { v[i] = p[lane + 32 * i]; s += v[i]; }
#pragma unroll
    for (int o = 16; o > 0; o >>= 1) s += __shfl_xor_sync(0xffffffffu, s, o);
    float mean = s * (1.f / CC);
    float q = 0.f;
#pragma unroll
    for (int i = 0; i < 6; i++) { float d = v[i] - mean; q += d * d; }
#pragma unroll
    for (int o = 16; o > 0; o >>= 1) q += __shfl_xor_sync(0xffffffffu, q, o);
    float inv = rsqrtf(q * (1.f / CC) + EPS_);
    __half* op = out + (size_t)row * CC;
#pragma unroll
    for (int i = 0; i < 6; i++) {
        int c = lane + 32 * i;
        op[c] = __float2half((v[i] - mean) * inv * w[c] + b[c]);
    }
}

// ----------------------------- mma GEMM --------------------------------------
// C[128,128] tile = Ahi[128,K] x Bhi[NP,K]^T, single fp16 term.
// BK=64, 3-stage cp.async pipeline (2 chunks prefetched), one sync per chunk.
// stage: A 16K | B 16K = 32KB; 3 stages = 96KB dyn smem, 2 CTA/SM.
#define STAGE_B 32768
template<int K, int MODE, int NREAL>
__global__ __launch_bounds__(256, 2)
void mma_gemm(const __half* __restrict__ A,
              const __half* __restrict__ Bhi,
              const float* __restrict__ bias,
              const float* __restrict__ aux,
              float* __restrict__ outp)
{
    extern __shared__ __align__(128) char dynsm[];
    constexpr int NCH = K / 64;

    const int tid  = threadIdx.x;
    const int lane = tid & 31;
    const int warp = tid >> 5;
    const int wm = warp & 3;
    const int wn = warp >> 2;
    const int blockN = blockIdx.x * 128;
    const int blockM = blockIdx.y * 128;
    const uint32_t sb0 = smem_u32(dynsm);

    const __half* aSrc[4];
    uint32_t aDst[4];
#pragma unroll
    for (int i = 0; i < 4; i++) {
        int idx = i * 256 + tid;
        int row = idx >> 3, u = idx & 7;
        int garow = (MODE == 0) ? g_rowmap[blockM + row] : (blockM + row);
        aSrc[i] = A + (size_t)garow * K + u * 8;
        aDst[i] = SWZ((uint32_t)(row * 128 + u * 16));
    }
    const __half* bSrc[4];
    uint32_t bDst[4];
#pragma unroll
    for (int i = 0; i < 4; i++) {
        int idx = i * 256 + tid;
        int n = idx >> 3, u = idx & 7;
        bSrc[i] = Bhi + (size_t)(blockN + n) * K + u * 8;
        bDst[i] = SWZ((uint32_t)(n * 128 + u * 16));
    }

    auto issue = [&](int c, int st) {
        const uint32_t sb = sb0 + st * STAGE_B;
#pragma unroll
        for (int i = 0; i < 4; i++)
            cp16(sb + aDst[i], aSrc[i] + c * 64);
#pragma unroll
        for (int i = 0; i < 4; i++)
            cp16(sb + 16384 + bDst[i], bSrc[i] + c * 64);
    };

    uint32_t oA[2], oB[4];
#pragma unroll
    for (int tm = 0; tm < 2; tm++)
        oA[tm] = (uint32_t)((wm * 32 + tm * 16 + (lane & 15)) * 128 + (lane >> 4) * 16);
#pragma unroll
    for (int g = 0; g < 4; g++)
        oB[g] = (uint32_t)((wn * 64 + g * 16 + (lane & 7) + ((lane >> 4) & 1) * 8) * 128
                           + ((lane >> 3) & 1) * 16);

    float Cr[2][8][4];
#pragma unroll
    for (int a = 0; a < 2; a++)
#pragma unroll
        for (int b = 0; b < 8; b++)
#pragma unroll
            for (int c = 0; c < 4; c++) Cr[a][b][c] = 0.f;

    issue(0, 0); cp_commit();
    if (NCH > 1) issue(1, 1);
    cp_commit();

    for (int c = 0; c < NCH; c++) {
        const int st = c % 3;
        cp_wait1();
        __syncthreads();
        if (c + 2 < NCH) issue(c + 2, (c + 2) % 3);
        cp_commit();

        const uint32_t aB = sb0 + st * STAGE_B;
        const uint32_t bB = aB + 16384;
#pragma unroll
        for (int k16 = 0; k16 < 4; k16++) {
            const uint32_t ko = k16 * 32;
            uint32_t Ah[2][4], Bh[4][4];
#pragma unroll
            for (int tm = 0; tm < 2; tm++)
                ldm4(Ah[tm], aB + SWZ(oA[tm] + ko));
#pragma unroll
            for (int g = 0; g < 4; g++)
                ldm4(Bh[g], bB + SWZ(oB[g] + ko));
#pragma unroll
            for (int tm = 0; tm < 2; tm++)
#pragma unroll
                for (int tn = 0; tn < 8; tn++)
                    mma16816(Cr[tm][tn], Ah[tm],
                             Bh[tn >> 1][(tn & 1) * 2], Bh[tn >> 1][(tn & 1) * 2 + 1]);
        }
    }

    // ------------------------------ epilogue --------------------------------
    const int r0 = blockM + wm * 32 + (lane >> 2);
    const int n0 = blockN + wn * 64 + 2 * (lane & 3);
#pragma unroll
    for (int tm = 0; tm < 2; tm++) {
#pragma unroll
        for (int tn = 0; tn < 8; tn++) {
            int n = n0 + tn * 8;
            if (n >= NREAL) continue;
            float bx = bias[n], by = bias[n + 1];
#pragma unroll
            for (int half_ = 0; half_ < 2; half_++) {
                int m = r0 + tm * 16 + half_ * 8;
                float vx = Cr[tm][tn][half_ * 2 + 0] + bx;
                float vy = Cr[tm][tn][half_ * 2 + 1] + by;
                if (MODE == 0) {
                    *(__half2*)(g_qkv + (size_t)m * 576 + n) = __floats2half2_rn(vx, vy);
                } else if (MODE == 1) {
                    size_t idx = (size_t)g_rowmap[m] * CC + n;
                    float2 a = *(const float2*)(aux + idx);
                    *(float2*)(g_xnew + idx) = make_float2(vx + a.x, vy + a.y);
                } else if (MODE == 2) {
                    vx = 0.5f * vx * (1.f + erff(vx * 0.70710678118654752f));
                    vy = 0.5f * vy * (1.f + erff(vy * 0.70710678118654752f));
                    *(__half2*)(g_hid + (size_t)m * HIDDEN + n) = __floats2half2_rn(vx, vy);
                } else {
                    size_t idx = (size_t)m * CC + n;
                    float2 a = *(const float2*)(g_xnew + idx);
                    *(float2*)(outp + idx) = make_float2(vx + a.x, vy + a.y);
                }
            }
        }
    }
}

// ------------------------------ attention -----------------------------------
// q in fp32 smem (stride 36), k/v in fp16 smem (stride 40 halves = 80B rows).
__global__ __launch_bounds__(256)
void attn_kernel(const float* __restrict__ rpb) {
    __shared__ __align__(16) float  sq[52 * 36];
    __shared__ __align__(16) __half sk[52 * 40];
    __shared__ __align__(16) __half sv[52 * 40];
    __shared__ float sS[NTOK * 50];
    __shared__ float srpb[169];
    __shared__ int   slabel[NTOK];

    const int bwin = blockIdx.x;
    const int head = blockIdx.y;
    const int tid  = threadIdx.x;
    const float scale = 0.17677669529663687f;

    const size_t rbase = (size_t)(bwin * NTOK) * 576 + head * HD_;
    for (int idx = tid; idx < NTOK * 16; idx += 256) {
        int tok = idx >> 4, d2 = (idx & 15) * 2;
        const __half* r = g_qkv + rbase + (size_t)tok * 576 + d2;
        float2 qf = __half22float2(*(const __half2*)r);
        sq[tok * 36 + d2]     = qf.x * scale;
        sq[tok * 36 + d2 + 1] = qf.y * scale;
        *(__half2*)(sk + tok * 40 + d2) = *(const __half2*)(r + 192);
        *(__half2*)(sv + tok * 40 + d2) = *(const __half2*)(r + 384);
    }
    for (int t = tid; t < 169; t += 256) srpb[t] = rpb[t * NH_ + head];
    if (tid < NTOK) {
        int w = bwin & 63;
        int wh = w >> 3, ww = w & 7;
        int r = tid / WS_, c = tid - r * WS_;
        int gh = wh * WS_ + r, gw = ww * WS_ + c;
        int rr = (gh < HH - WS_) ? 0 : (gh < HH - SS_) ? 1 : 2;
        int cc = (gw < WW_ - WS_) ? 0 : (gw < WW_ - SS_) ? 1 : 2;
        slabel[tid] = rr * 3 + cc;
    }
    for (int t = tid; t < 3 * 40; t += 256) {         // zero pad rows 49..51
        sk[49 * 40 + t] = __half(0);
        sv[49 * 40 + t] = __half(0);
    }
    __syncthreads();

    // S = q k^T + bias + mask (4 j per thread, 8 d per step)
    for (int e = tid; e < NTOK * 13; e += 256) {
        int i = e / 13, j0 = (e - i * 13) * 4;
        float acc[4] = {0.f, 0.f, 0.f, 0.f};
        const float* qi = &sq[i * 36];
#pragma unroll
        for (int d8 = 0; d8 < 4; d8++) {
            float4 qa = *(const float4*)(qi + d8 * 8);
            float4 qb = *(const float4*)(qi + d8 * 8 + 4);
#pragma unroll
            for (int t = 0; t < 4; t++) {
                uint4 kv = *(const uint4*)(sk + (j0 + t) * 40 + d8 * 8);
                const __half2* kh = (const __half2*)&kv;
                float2 f0 = __half22float2(kh[0]);
                float2 f1 = __half22float2(kh[1]);
                float2 f2 = __half22float2(kh[2]);
                float2 f3 = __half22float2(kh[3]);
                acc[t] += qa.x * f0.x + qa.y * f0.y + qa.z * f1.x + qa.w * f1.y
                        + qb.x * f2.x + qb.y * f2.y + qb.z * f3.x + qb.w * f3.y;
            }
        }
        int ri = i / WS_, ci = i - ri * WS_;
        int li = slabel[i];
#pragma unroll
        for (int t = 0; t < 4; t++) {
            int j = j0 + t;
            if (j < NTOK) {
                int rj = j / WS_, cj = j - rj * WS_;
                float a = acc[t] + srpb[(ri - rj + 6) * 13 + (ci - cj + 6)];
                if (li != slabel[j]) a -= 100.f;
                sS[i * 50 + j] = a;
            }
        }
    }
    __syncthreads();

    // softmax: warp per row
    {
        int warp = tid >> 5, lane = tid & 31;
        for (int i = warp; i < NTOK; i += 8) {
            float mx = -1e30f;
            for (int j = lane; j < NTOK; j += 32) mx = fmaxf(mx, sS[i * 50 + j]);
#pragma unroll
            for (int o = 16; o > 0; o >>= 1) mx = fmaxf(mx, __shfl_xor_sync(0xffffffffu, mx, o));
            float s = 0.f;
            for (int j = lane; j < NTOK; j += 32) {
                float e = __expf(sS[i * 50 + j] - mx);
                sS[i * 50 + j] = e;
                s += e;
            }
#pragma unroll
            for (int o = 16; o > 0; o >>= 1) s += __shfl_xor_sync(0xffffffffu, s, o);
            float inv = 1.f / s;
            for (int j = lane; j < NTOK; j += 32) sS[i * 50 + j] *= inv;
        }
    }
    __syncthreads();

    // O = P V (8 d per thread), fp16 out
    for (int e = tid; e < NTOK * 4; e += 256) {
        int i = e >> 2, d0 = (e & 3) * 8;
        float acc[8] = {0.f, 0.f, 0.f, 0.f, 0.f, 0.f, 0.f, 0.f};
        const float* Si = &sS[i * 50];
#pragma unroll
        for (int j = 0; j < NTOK; j++) {
            float s_ = Si[j];
            uint4 vv = *(const uint4*)(sv + j * 40 + d0);
            const __half2* vh = (const __half2*)&vv;
            float2 f0 = __half22float2(vh[0]);
            float2 f1 = __half22float2(vh[1]);
            float2 f2 = __half22float2(vh[2]);
            float2 f3 = __half22float2(vh[3]);
            acc[0] += s_ * f0.x; acc[1] += s_ * f0.y;
            acc[2] += s_ * f1.x; acc[3] += s_ * f1.y;
            acc[4] += s_ * f2.x; acc[5] += s_ * f2.y;
            acc[6] += s_ * f3.x; acc[7] += s_ * f3.y;
        }
        uint4 o;
        o.x = h2u(__floats2half2_rn(acc[0], acc[1]));
        o.y = h2u(__floats2half2_rn(acc[2], acc[3]));
        o.z = h2u(__floats2half2_rn(acc[4], acc[5]));
        o.w = h2u(__floats2half2_rn(acc[6], acc[7]));
        *(uint4*)(g_attn + (size_t)(bwin * NTOK + i) * CC + head * HD_ + d0) = o;
    }
}

// ------------------------------- launch -------------------------------------
extern "C" void kernel_launch(void* const* d_in, const int* in_sizes, int n_in,
                              void* d_out, int out_size) {
    const float* x       = (const float*)d_in[0];
    const float* norm1_w = (const float*)d_in[1];
    const float* norm1_b = (const float*)d_in[2];
    const float* qkv_w   = (const float*)d_in[3];
    const float* qkv_b   = (const float*)d_in[4];
    const float* rpb     = (const float*)d_in[5];
    const float* proj_w  = (const float*)d_in[6];
    const float* proj_b  = (const float*)d_in[7];
    const float* norm2_w = (const float*)d_in[8];
    const float* norm2_b = (const float*)d_in[9];
    const float* fc1_w   = (const float*)d_in[10];
    const float* fc1_b   = (const float*)d_in[11];
    const float* fc2_w   = (const float*)d_in[12];
    const float* fc2_b   = (const float*)d_in[13];
    float* out = (float*)d_out;

    __half *p_ln, *p_attn, *p_hid, *p_wqkv, *p_wproj, *p_wfc1, *p_wfc2;
    float *p_xnew;
    cudaGetSymbolAddress((void**)&p_ln,    g_ln);
    cudaGetSymbolAddress((void**)&p_attn,  g_attn);
    cudaGetSymbolAddress((void**)&p_hid,   g_hid);
    cudaGetSymbolAddress((void**)&p_xnew,  g_xnew);
    cudaGetSymbolAddress((void**)&p_wqkv,  g_wqkv);
    cudaGetSymbolAddress((void**)&p_wproj, g_wproj);
    cudaGetSymbolAddress((void**)&p_wfc1,  g_wfc1);
    cudaGetSymbolAddress((void**)&p_wfc2,  g_wfc2);

    const int SMEM = 3 * STAGE_B;   // 96 KB
    cudaFuncSetAttribute(mma_gemm<192,0,576>, cudaFuncAttributeMaxDynamicSharedMemorySize, SMEM);
    cudaFuncSetAttribute(mma_gemm<192,1,192>, cudaFuncAttributeMaxDynamicSharedMemorySize, SMEM);
    cudaFuncSetAttribute(mma_gemm<192,2,768>, cudaFuncAttributeMaxDynamicSharedMemorySize, SMEM);
    cudaFuncSetAttribute(mma_gemm<768,3,192>, cudaFuncAttributeMaxDynamicSharedMemorySize, SMEM);

    // order: QKV GEMM at launch index 3 so ncu (-s 5, harness offset ~2) captures it
    ln_kernel<<<MROWS / 8, 256>>>(x, norm1_w, norm1_b, p_ln);                     // 0
    whalf_kernel<<<(640 * 192 + 255) / 256, 256>>>(qkv_w, p_wqkv, 192, 576, 640); // 1
    rowmap_kernel<<<(MROWS + 255) / 256, 256>>>();                                // 2
    mma_gemm<192, 0, 576><<<dim3(5, 1568), 256, SMEM>>>(p_ln, p_wqkv, qkv_b, nullptr, nullptr); // 3

    attn_kernel<<<dim3(NWIN, NH_), 256>>>(rpb);                                   // 4

    whalf_kernel<<<(256 * 192 + 255) / 256, 256>>>(proj_w, p_wproj, 192, 192, 256); // 5
    mma_gemm<192, 1, 192><<<dim3(2, 1568), 256, SMEM>>>(p_attn, p_wproj, proj_b, x, nullptr); // 6

    ln_kernel<<<MROWS / 8, 256>>>(p_xnew, norm2_w, norm2_b, p_ln);                // 7

    whalf_kernel<<<(768 * 192 + 255) / 256, 256>>>(fc1_w, p_wfc1, 192, 768, 768); // 8
    mma_gemm<192, 2, 768><<<dim3(6, 1568), 256, SMEM>>>(p_ln, p_wfc1, fc1_b, nullptr, nullptr); // 9

    whalf_kernel<<<(256 * 768 + 255) / 256, 256>>>(fc2_w, p_wfc2, 768, 192, 256); // 10
    mma_gemm<768, 3, 192><<<dim3(2, 1568), 256, SMEM>>>(p_hid, p_wfc2, fc2_b, nullptr, out); // 11
}

// round 9
// speedup vs baseline: 3.2109x; 1.6016x over previous
#include <cuda_runtime.h>
#include <cuda_fp16.h>
#include <math.h>
#include <stdint.h>

// ---------------------------------------------------------------------------
// Swin block: single-term fp16 HMMA GEMMs (3-stage cp.async pipeline) +
// fully tensorized windowed attention (HMMA S & PV, register softmax).
// ---------------------------------------------------------------------------

#define BATCH   64
#define HH      56
#define WW_     56
#define CC      192
#define WS_     7
#define SS_     3
#define NH_     6
#define HD_     32
#define NTOK    49
#define NWIN    4096
#define MROWS   200704
#define HIDDEN  768
#define EPS_    1e-5f

// ------------------------------- scratch -----------------------------------
__device__ __half g_ln  [(size_t)MROWS * 192];
__device__ __half g_attn[(size_t)MROWS * 192];
__device__ __half g_hid [(size_t)MROWS * 768];
__device__ __half g_qkv [(size_t)MROWS * 576];
__device__ float g_xnew[(size_t)MROWS * CC];
__device__ __half g_wqkv [640 * 192];
__device__ __half g_wproj[256 * 192];
__device__ __half g_wfc1 [768 * 192];
__device__ __half g_wfc2 [256 * 768];

// ------------------------------ helpers -------------------------------------
__device__ __forceinline__ uint32_t smem_u32(const void* p) {
    uint32_t a;
    asm("{ .reg .u64 t; cvta.to.shared.u64 t, %1; cvt.u32.u64 %0, t; }"
        : "=r"(a) : "l"(p));
    return a;
}
#define SWZ(o) ((o) ^ (((o) >> 3) & 0x70))

__device__ __forceinline__ void cp16(uint32_t dst, const void* src) {
    asm volatile("cp.async.cg.shared.global [%0], [%1], 16;"
                 :: "r"(dst), "l"(src));
}
__device__ __forceinline__ void cp_commit() {
    asm volatile("cp.async.commit_group;" ::: "memory");
}
__device__ __forceinline__ void cp_wait1() {
    asm volatile("cp.async.wait_group 1;" ::: "memory");
}
__device__ __forceinline__ void ldm4(uint32_t* r, uint32_t addr) {
    asm volatile("ldmatrix.sync.aligned.m8n8.x4.shared.b16 {%0,%1,%2,%3}, [%4];"
                 : "=r"(r[0]), "=r"(r[1]), "=r"(r[2]), "=r"(r[3]) : "r"(addr));
}
__device__ __forceinline__ void mma16816(float* c, const uint32_t* a,
                                         uint32_t b0, uint32_t b1) {
    asm volatile(
        "mma.sync.aligned.m16n8k16.row.col.f32.f16.f16.f32 "
        "{%0,%1,%2,%3}, {%4,%5,%6,%7}, {%8,%9}, {%0,%1,%2,%3};"
        : "+f"(c[0]), "+f"(c[1]), "+f"(c[2]), "+f"(c[3])
        : "r"(a[0]), "r"(a[1]), "r"(a[2]), "r"(a[3]), "r"(b0), "r"(b1));
}
__device__ __forceinline__ uint32_t h2u(__half2 v) { return *(uint32_t*)&v; }

// inline shift/window permutation: window-order row -> natural row
__device__ __forceinline__ int rowmap_of(int m) {
    int bwin = m / NTOK, tok = m - bwin * NTOK;
    int b = bwin >> 6, w = bwin & 63;
    int wh = w >> 3, ww = w & 7;
    int r = tok / WS_, c = tok - r * WS_;
    int oh = wh * WS_ + r + SS_; if (oh >= HH)  oh -= HH;
    int ow = ww * WS_ + c + SS_; if (ow >= WW_) ow -= WW_;
    return b * (HH * WW_) + oh * WW_ + ow;
}

// -------------------------- small prep kernels ------------------------------
__global__ void whalf_kernel(const float* __restrict__ W,
                             __half* __restrict__ out, int Kd, int Nd, int NP) {
    int idx = blockIdx.x * 256 + threadIdx.x;
    if (idx >= NP * Kd) return;
    int n = idx / Kd, k = idx - n * Kd;
    out[idx] = (n < Nd) ? __float2half(W[(size_t)k * Nd + n]) : __half(0);
}

__global__ void ln_kernel(const float* __restrict__ in,
                          const float* __restrict__ w,
                          const float* __restrict__ b,
                          __half* __restrict__ out) {
    int row  = blockIdx.x * 8 + (threadIdx.x >> 5);
    int lane = threadIdx.x & 31;
    const float* p = in + (size_t)row * CC;
    float v[6];
    float s = 0.f;
#pragma unroll
    for (int i = 0; i < 6; i++) { v[i] = p[lane + 32 * i]; s += v[i]; }
#pragma unroll
    for (int o = 16; o > 0; o >>= 1) s += __shfl_xor_sync(0xffffffffu, s, o);
    float mean = s * (1.f / CC);
    float q = 0.f;
#pragma unroll
    for (int i = 0; i < 6; i++) { float d = v[i] - mean; q += d * d; }
#pragma unroll
    for (int o = 16; o > 0; o >>= 1) q += __shfl_xor_sync(0xffffffffu, q, o);
    float inv = rsqrtf(q * (1.f / CC) + EPS_);
    __half* op = out + (size_t)row * CC;
#pragma unroll
    for (int i = 0; i < 6; i++) {
        int c = lane + 32 * i;
        op[c] = __float2half((v[i] - mean) * inv * w[c] + b[c]);
    }
}

// ----------------------------- mma GEMM --------------------------------------
#define STAGE_B 32768
template<int K, int MODE, int NREAL>
__global__ __launch_bounds__(256, 2)
void mma_gemm(const __half* __restrict__ A,
              const __half* __restrict__ Bhi,
              const float* __restrict__ bias,
              const float* __restrict__ aux,
              float* __restrict__ outp)
{
    extern __shared__ __align__(128) char dynsm[];
    constexpr int NCH = K / 64;

    const int tid  = threadIdx.x;
    const int lane = tid & 31;
    const int warp = tid >> 5;
    const int wm = warp & 3;
    const int wn = warp >> 2;
    const int blockN = blockIdx.x * 128;
    const int blockM = blockIdx.y * 128;
    const uint32_t sb0 = smem_u32(dynsm);

    const __half* aSrc[4];
    uint32_t aDst[4];
#pragma unroll
    for (int i = 0; i < 4; i++) {
        int idx = i * 256 + tid;
        int row = idx >> 3, u = idx & 7;
        int garow = (MODE == 0) ? rowmap_of(blockM + row) : (blockM + row);
        aSrc[i] = A + (size_t)garow * K + u * 8;
        aDst[i] = SWZ((uint32_t)(row * 128 + u * 16));
    }
    const __half* bSrc[4];
    uint32_t bDst[4];
#pragma unroll
    for (int i = 0; i < 4; i++) {
        int idx = i * 256 + tid;
        int n = idx >> 3, u = idx & 7;
        bSrc[i] = Bhi + (size_t)(blockN + n) * K + u * 8;
        bDst[i] = SWZ((uint32_t)(n * 128 + u * 16));
    }

    auto issue = [&](int c, int st) {
        const uint32_t sb = sb0 + st * STAGE_B;
#pragma unroll
        for (int i = 0; i < 4; i++)
            cp16(sb + aDst[i], aSrc[i] + c * 64);
#pragma unroll
        for (int i = 0; i < 4; i++)
            cp16(sb + 16384 + bDst[i], bSrc[i] + c * 64);
    };

    uint32_t oA[2], oB[4];
#pragma unroll
    for (int tm = 0; tm < 2; tm++)
        oA[tm] = (uint32_t)((wm * 32 + tm * 16 + (lane & 15)) * 128 + (lane >> 4) * 16);
#pragma unroll
    for (int g = 0; g < 4; g++)
        oB[g] = (uint32_t)((wn * 64 + g * 16 + (lane & 7) + ((lane >> 4) & 1) * 8) * 128
                           + ((lane >> 3) & 1) * 16);

    float Cr[2][8][4];
#pragma unroll
    for (int a = 0; a < 2; a++)
#pragma unroll
        for (int b = 0; b < 8; b++)
#pragma unroll
            for (int c = 0; c < 4; c++) Cr[a][b][c] = 0.f;

    issue(0, 0); cp_commit();
    if (NCH > 1) issue(1, 1);
    cp_commit();

    for (int c = 0; c < NCH; c++) {
        const int st = c % 3;
        cp_wait1();
        __syncthreads();
        if (c + 2 < NCH) issue(c + 2, (c + 2) % 3);
        cp_commit();

        const uint32_t aB = sb0 + st * STAGE_B;
        const uint32_t bB = aB + 16384;
#pragma unroll
        for (int k16 = 0; k16 < 4; k16++) {
            const uint32_t ko = k16 * 32;
            uint32_t Ah[2][4], Bh[4][4];
#pragma unroll
            for (int tm = 0; tm < 2; tm++)
                ldm4(Ah[tm], aB + SWZ(oA[tm] + ko));
#pragma unroll
            for (int g = 0; g < 4; g++)
                ldm4(Bh[g], bB + SWZ(oB[g] + ko));
#pragma unroll
            for (int tm = 0; tm < 2; tm++)
#pragma unroll
                for (int tn = 0; tn < 8; tn++)
                    mma16816(Cr[tm][tn], Ah[tm],
                             Bh[tn >> 1][(tn & 1) * 2], Bh[tn >> 1][(tn & 1) * 2 + 1]);
        }
    }

    const int r0 = blockM + wm * 32 + (lane >> 2);
    const int n0 = blockN + wn * 64 + 2 * (lane & 3);
#pragma unroll
    for (int tm = 0; tm < 2; tm++) {
#pragma unroll
        for (int tn = 0; tn < 8; tn++) {
            int n = n0 + tn * 8;
            if (n >= NREAL) continue;
            float bx = bias[n], by = bias[n + 1];
#pragma unroll
            for (int half_ = 0; half_ < 2; half_++) {
                int m = r0 + tm * 16 + half_ * 8;
                float vx = Cr[tm][tn][half_ * 2 + 0] + bx;
                float vy = Cr[tm][tn][half_ * 2 + 1] + by;
                if (MODE == 0) {
                    *(__half2*)(g_qkv + (size_t)m * 576 + n) = __floats2half2_rn(vx, vy);
                } else if (MODE == 1) {
                    size_t idx = (size_t)rowmap_of(m) * CC + n;
                    float2 a = *(const float2*)(aux + idx);
                    *(float2*)(g_xnew + idx) = make_float2(vx + a.x, vy + a.y);
                } else if (MODE == 2) {
                    vx = 0.5f * vx * (1.f + erff(vx * 0.70710678118654752f));
                    vy = 0.5f * vy * (1.f + erff(vy * 0.70710678118654752f));
                    *(__half2*)(g_hid + (size_t)m * HIDDEN + n) = __floats2half2_rn(vx, vy);
                } else {
                    size_t idx = (size_t)m * CC + n;
                    float2 a = *(const float2*)(g_xnew + idx);
                    *(float2*)(outp + idx) = make_float2(vx + a.x, vy + a.y);
                }
            }
        }
    }
}

// ------------------------------ attention (HMMA) -----------------------------
// Block per window; 8 warps = 2 heads x 4 m16-blocks; loop 3 head pairs.
// S = QK^T via mma (16x64 per warp), softmax in registers, P->A frag reuse,
// O = PV via mma with V stored transposed.
__global__ __launch_bounds__(256)
void attn_kernel(const float* __restrict__ rpb) {
    __shared__ __align__(16) __half sq [2][64 * 40];
    __shared__ __align__(16) __half skk[2][64 * 40];
    __shared__ __align__(16) __half svt[2][32 * 72];
    __shared__ float srpb[6 * 169];
    __shared__ int   slabel[64];

    const int bwin = blockIdx.x;
    const int tid  = threadIdx.x;
    const int lane = tid & 31;
    const int warp = tid >> 5;
    const int hw = warp >> 2;      // head within pair
    const int mb = warp & 3;       // m16 block
    const float scale = 0.17677669529663687f;

    for (int idx = tid; idx < 6 * 169; idx += 256)
        srpb[idx] = rpb[(idx % 169) * NH_ + idx / 169];
    if (tid < 64) {
        int label = 0;
        if (tid < NTOK) {
            int w = bwin & 63;
            int wh = w >> 3, ww = w & 7;
            int r = tid / WS_, c = tid - r * WS_;
            int gh = wh * WS_ + r, gw = ww * WS_ + c;
            int rr = (gh < HH - WS_) ? 0 : (gh < HH - SS_) ? 1 : 2;
            int cc = (gw < WW_ - WS_) ? 0 : (gw < WW_ - SS_) ? 1 : 2;
            label = rr * 3 + cc;
        }
        slabel[tid] = label;
    }

    const int i0 = mb * 16 + (lane >> 2);
    const int i1 = i0 + 8;
    const int ri0 = i0 / WS_, ci0 = i0 - ri0 * WS_;
    const int ri1 = i1 / WS_, ci1 = i1 - ri1 * WS_;

    for (int p = 0; p < 3; p++) {
        __syncthreads();
        // zero V^T (padding tokens must be 0)
        for (int t = tid; t < (2 * 32 * 72) / 2; t += 256)
            ((uint32_t*)svt)[t] = 0;
        __syncthreads();
        // load q (scaled), k, v^T for 2 heads
        for (int idx = tid; idx < 2 * NTOK * 16; idx += 256) {
            int h = (idx >= NTOK * 16);
            int rem = idx - h * NTOK * 16;
            int tok = rem >> 4, d2 = (rem & 15) * 2;
            const __half* src = g_qkv + (size_t)(bwin * NTOK + tok) * 576
                                + (p * 2 + h) * 32 + d2;
            float2 qf = __half22float2(*(const __half2*)src);
            *(__half2*)(&sq[h][tok * 40 + d2]) = __floats2half2_rn(qf.x * scale, qf.y * scale);
            *(__half2*)(&skk[h][tok * 40 + d2]) = *(const __half2*)(src + 192);
            __half2 vv = *(const __half2*)(src + 384);
            svt[h][d2 * 72 + tok]       = __low2half(vv);
            svt[h][(d2 + 1) * 72 + tok] = __high2half(vv);
        }
        __syncthreads();

        const int head = p * 2 + hw;
        const float* rp = &srpb[head * 169];
        const uint32_t qb = smem_u32(sq[hw]);
        const uint32_t kb = smem_u32(skk[hw]);
        const uint32_t vb = smem_u32(svt[hw]);

        // ---- S = Q K^T (16x64 per warp) ----
        float Cs[8][4];
#pragma unroll
        for (int f = 0; f < 8; f++)
#pragma unroll
            for (int s = 0; s < 4; s++) Cs[f][s] = 0.f;
#pragma unroll
        for (int k16 = 0; k16 < 2; k16++) {
            uint32_t Ah[4];
            ldm4(Ah, qb + ((mb * 16 + (lane & 15)) * 40 + (lane >> 4) * 8 + k16 * 16) * 2);
#pragma unroll
            for (int g = 0; g < 4; g++) {
                uint32_t Bf[4];
                ldm4(Bf, kb + ((g * 16 + (lane & 7) + ((lane >> 4) & 1) * 8) * 40
                               + ((lane >> 3) & 1) * 8 + k16 * 16) * 2);
                mma16816(Cs[g * 2 + 0], Ah, Bf[0], Bf[1]);
                mma16816(Cs[g * 2 + 1], Ah, Bf[2], Bf[3]);
            }
        }

        // ---- bias + mask ----
        const int li0 = slabel[i0];
        const int li1 = slabel[i1];
#pragma unroll
        for (int f = 0; f < 8; f++) {
            int jb = f * 8 + (lane & 3) * 2;
#pragma unroll
            for (int s = 0; s < 2; s++) {
                int j = jb + s;
                if (j < NTOK) {
                    int rj = j / WS_, cj = j - rj * WS_;
                    int lj = slabel[j];
                    if (i0 < NTOK) {
                        float b0 = rp[(ri0 - rj + 6) * 13 + (ci0 - cj + 6)];
                        Cs[f][s] += b0 - (li0 != lj ? 100.f : 0.f);
                    } else Cs[f][s] = -1e30f;
                    if (i1 < NTOK) {
                        float b1 = rp[(ri1 - rj + 6) * 13 + (ci1 - cj + 6)];
                        Cs[f][2 + s] += b1 - (li1 != lj ? 100.f : 0.f);
                    } else Cs[f][2 + s] = -1e30f;
                } else {
                    Cs[f][s] = -1e30f;
                    Cs[f][2 + s] = -1e30f;
                }
            }
        }

        // ---- softmax in registers (quad shuffle) ----
        float mx0 = -1e30f, mx1 = -1e30f;
#pragma unroll
        for (int f = 0; f < 8; f++) {
            mx0 = fmaxf(mx0, fmaxf(Cs[f][0], Cs[f][1]));
            mx1 = fmaxf(mx1, fmaxf(Cs[f][2], Cs[f][3]));
        }
        mx0 = fmaxf(mx0, __shfl_xor_sync(0xffffffffu, mx0, 1));
        mx0 = fmaxf(mx0, __shfl_xor_sync(0xffffffffu, mx0, 2));
        mx1 = fmaxf(mx1, __shfl_xor_sync(0xffffffffu, mx1, 1));
        mx1 = fmaxf(mx1, __shfl_xor_sync(0xffffffffu, mx1, 2));
        float sum0 = 0.f, sum1 = 0.f;
#pragma unroll
        for (int f = 0; f < 8; f++) {
            Cs[f][0] = __expf(Cs[f][0] - mx0);
            Cs[f][1] = __expf(Cs[f][1] - mx0);
            Cs[f][2] = __expf(Cs[f][2] - mx1);
            Cs[f][3] = __expf(Cs[f][3] - mx1);
            sum0 += Cs[f][0] + Cs[f][1];
            sum1 += Cs[f][2] + Cs[f][3];
        }
        sum0 += __shfl_xor_sync(0xffffffffu, sum0, 1);
        sum0 += __shfl_xor_sync(0xffffffffu, sum0, 2);
        sum1 += __shfl_xor_sync(0xffffffffu, sum1, 1);
        sum1 += __shfl_xor_sync(0xffffffffu, sum1, 2);
        const float inv0 = 1.f / sum0;
        const float inv1 = 1.f / sum1;

        // ---- P (C-frags) -> A-frags ----
        uint32_t Pa[4][4];
#pragma unroll
        for (int f2 = 0; f2 < 4; f2++) {
            Pa[f2][0] = h2u(__floats2half2_rn(Cs[2 * f2][0],     Cs[2 * f2][1]));
            Pa[f2][1] = h2u(__floats2half2_rn(Cs[2 * f2][2],     Cs[2 * f2][3]));
            Pa[f2][2] = h2u(__floats2half2_rn(Cs[2 * f2 + 1][0], Cs[2 * f2 + 1][1]));
            Pa[f2][3] = h2u(__floats2half2_rn(Cs[2 * f2 + 1][2], Cs[2 * f2 + 1][3]));
        }

        // ---- O = P V ----
        float Co[4][4];
#pragma unroll
        for (int f = 0; f < 4; f++)
#pragma unroll
            for (int s = 0; s < 4; s++) Co[f][s] = 0.f;
#pragma unroll
        for (int k16 = 0; k16 < 4; k16++) {
#pragma unroll
            for (int g = 0; g < 2; g++) {
                uint32_t Bv[4];
                ldm4(Bv, vb + ((g * 16 + (lane & 7) + ((lane >> 4) & 1) * 8) * 72
                               + ((lane >> 3) & 1) * 8 + k16 * 16) * 2);
                mma16816(Co[g * 2 + 0], Pa[k16], Bv[0], Bv[1]);
                mma16816(Co[g * 2 + 1], Pa[k16], Bv[2], Bv[3]);
            }
        }

        // ---- store O (fp16, window-order) ----
#pragma unroll
        for (int f = 0; f < 4; f++) {
            int d = f * 8 + (lane & 3) * 2;
            if (i0 < NTOK)
                *(__half2*)(g_attn + (size_t)(bwin * NTOK + i0) * CC + head * 32 + d) =
                    __floats2half2_rn(Co[f][0] * inv0, Co[f][1] * inv0);
            if (i1 < NTOK)
                *(__half2*)(g_attn + (size_t)(bwin * NTOK + i1) * CC + head * 32 + d) =
                    __floats2half2_rn(Co[f][2] * inv1, Co[f][3] * inv1);
        }
    }
}

// ------------------------------- launch -------------------------------------
extern "C" void kernel_launch(void* const* d_in, const int* in_sizes, int n_in,
                              void* d_out, int out_size) {
    const float* x       = (const float*)d_in[0];
    const float* norm1_w = (const float*)d_in[1];
    const float* norm1_b = (const float*)d_in[2];
    const float* qkv_w   = (const float*)d_in[3];
    const float* qkv_b   = (const float*)d_in[4];
    const float* rpb     = (const float*)d_in[5];
    const float* proj_w  = (const float*)d_in[6];
    const float* proj_b  = (const float*)d_in[7];
    const float* norm2_w = (const float*)d_in[8];
    const float* norm2_b = (const float*)d_in[9];
    const float* fc1_w   = (const float*)d_in[10];
    const float* fc1_b   = (const float*)d_in[11];
    const float* fc2_w   = (const float*)d_in[12];
    const float* fc2_b   = (const float*)d_in[13];
    float* out = (float*)d_out;

    __half *p_ln, *p_attn, *p_hid, *p_wqkv, *p_wproj, *p_wfc1, *p_wfc2;
    float *p_xnew;
    cudaGetSymbolAddress((void**)&p_ln,    g_ln);
    cudaGetSymbolAddress((void**)&p_attn,  g_attn);
    cudaGetSymbolAddress((void**)&p_hid,   g_hid);
    cudaGetSymbolAddress((void**)&p_xnew,  g_xnew);
    cudaGetSymbolAddress((void**)&p_wqkv,  g_wqkv);
    cudaGetSymbolAddress((void**)&p_wproj, g_wproj);
    cudaGetSymbolAddress((void**)&p_wfc1,  g_wfc1);
    cudaGetSymbolAddress((void**)&p_wfc2,  g_wfc2);

    const int SMEM = 3 * STAGE_B;   // 96 KB
    cudaFuncSetAttribute(mma_gemm<192,0,576>, cudaFuncAttributeMaxDynamicSharedMemorySize, SMEM);
    cudaFuncSetAttribute(mma_gemm<192,1,192>, cudaFuncAttributeMaxDynamicSharedMemorySize, SMEM);
    cudaFuncSetAttribute(mma_gemm<192,2,768>, cudaFuncAttributeMaxDynamicSharedMemorySize, SMEM);
    cudaFuncSetAttribute(mma_gemm<768,3,192>, cudaFuncAttributeMaxDynamicSharedMemorySize, SMEM);

    // attn_kernel at launch index 3 for ncu capture
    ln_kernel<<<MROWS / 8, 256>>>(x, norm1_w, norm1_b, p_ln);                     // 0
    whalf_kernel<<<(640 * 192 + 255) / 256, 256>>>(qkv_w, p_wqkv, 192, 576, 640); // 1
    mma_gemm<192, 0, 576><<<dim3(5, 1568), 256, SMEM>>>(p_ln, p_wqkv, qkv_b, nullptr, nullptr); // 2
    attn_kernel<<<NWIN, 256>>>(rpb);                                              // 3

    whalf_kernel<<<(256 * 192 + 255) / 256, 256>>>(proj_w, p_wproj, 192, 192, 256); // 4
    mma_gemm<192, 1, 192><<<dim3(2, 1568), 256, SMEM>>>(p_attn, p_wproj, proj_b, x, nullptr); // 5

    ln_kernel<<<MROWS / 8, 256>>>(p_xnew, norm2_w, norm2_b, p_ln);                // 6

    whalf_kernel<<<(768 * 192 + 255) / 256, 256>>>(fc1_w, p_wfc1, 192, 768, 768); // 7
    mma_gemm<192, 2, 768><<<dim3(6, 1568), 256, SMEM>>>(p_ln, p_wfc1, fc1_b, nullptr, nullptr); // 8

    whalf_kernel<<<(256 * 768 + 255) / 256, 256>>>(fc2_w, p_wfc2, 768, 192, 256); // 9
    mma_gemm<768, 3, 192><<<dim3(2, 1568), 256, SMEM>>>(p_hid, p_wfc2, fc2_b, nullptr, out); // 10
}